// round 7
// baseline (speedup 1.0000x reference)
#include <cuda_runtime.h>
#include <cstdint>

#define SEQ   4096
#define BATCH 64
#define INP   64
#define HID   256
#define G3    768
#define BG    32          // batch columns (2 batches each)
#define HG    8           // hidden groups (32 units each)
#define NCTA  (BG*HG)     // 256 scan CTAs, occupancy 2 -> all co-resident

// Scratch (static device allocations are the sanctioned workaround)
__device__ float d_xg[(size_t)SEQ * G3 * BATCH];     // [s][g][b]
__device__ float d_hbuf[2 * BG * HID * 2];           // [par][bg][u][b2]
__device__ float d_fcp[(size_t)NCTA * SEQ * 2];      // [(bg*8+hg)][t][b2]
__device__ unsigned int d_tag[NCTA * 8];             // 32B-strided epochs

__device__ __forceinline__ void fma2(unsigned long long& acc,
                                     unsigned long long a,
                                     unsigned long long b) {
    asm("fma.rn.f32x2 %0, %1, %2, %0;" : "+l"(acc) : "l"(a), "l"(b));
}
__device__ __forceinline__ unsigned long long pk(float a, float b) {
    unsigned long long r;
    asm("mov.b64 %0, {%1, %2};" : "=l"(r) : "f"(a), "f"(b));
    return r;
}
__device__ __forceinline__ float2 unpk(unsigned long long v) {
    float lo, hi;
    asm("mov.b64 {%0, %1}, %2;" : "=f"(lo), "=f"(hi) : "l"(v));
    return make_float2(lo, hi);
}

// ---------------------------------------------------------------------------
// Kernel A: xg[s][g][b] = sum_i x[s][b][i] * w_ih[g][i] + b_ih[g]
// ---------------------------------------------------------------------------
__global__ void __launch_bounds__(256) xg_kernel(const float* __restrict__ x,
                                                 const float* __restrict__ w_ih,
                                                 const float* __restrict__ b_ih) {
    __shared__ float xs[INP][BATCH + 1];
    __shared__ float ws[64][INP];
    const int s   = blockIdx.x;
    const int g0  = blockIdx.y * 64;
    const int tid = threadIdx.x;

    const float* xsrc = x + (size_t)s * BATCH * INP;
    for (int idx = tid; idx < BATCH * INP; idx += 256) {
        int b = idx >> 6, i = idx & 63;
        xs[i][b] = xsrc[idx];
    }
    const float* wsrc = w_ih + (size_t)g0 * INP;
    for (int idx = tid; idx < 64 * INP; idx += 256)
        ws[idx >> 6][idx & 63] = wsrc[idx];
    __syncthreads();

    const int b  = tid & 63;
    const int gg = tid >> 6;
    float xr[INP];
#pragma unroll
    for (int i = 0; i < INP; i++) xr[i] = xs[i][b];

    float acc[16];
#pragma unroll
    for (int u = 0; u < 16; u++) acc[u] = 0.0f;
    const int gb = gg * 16;
#pragma unroll
    for (int i4 = 0; i4 < INP / 4; i4++) {
#pragma unroll
        for (int u = 0; u < 16; u++) {
            float4 w4 = *(const float4*)&ws[gb + u][i4 * 4];
            acc[u] += w4.x * xr[i4 * 4 + 0];
            acc[u] += w4.y * xr[i4 * 4 + 1];
            acc[u] += w4.z * xr[i4 * 4 + 2];
            acc[u] += w4.w * xr[i4 * 4 + 3];
        }
    }
    float* dst = d_xg + ((size_t)s * G3 + g0) * BATCH;
#pragma unroll
    for (int u = 0; u < 16; u++) {
        int gl = gb + u;
        __stcs(&dst[(size_t)gl * BATCH + b], acc[u] + b_ih[g0 + gl]);
    }
}

// ---------------------------------------------------------------------------
// Kernel B: batch-tiled persistent GRU scan, occupancy 2 (two independent
// batch-column chains per SM hide each other's L2 sync latency).
// CTA c = bg*8+hg: 2 batches x 32 hidden units, weights register-resident.
// Per-warp poll+gather: every lane acquire-polls tag (lane&7) of own column,
// then the warp immediately gathers its 32 units of h(t-1) into smem.
// ---------------------------------------------------------------------------
__global__ void __launch_bounds__(256, 2) scan_kernel(const float* __restrict__ w_hh,
                                                      const float* __restrict__ b_hh,
                                                      const float* __restrict__ fc_w) {
    __shared__ float hsm[2][HID];          // [b_local][k]
    __shared__ float sout[3][2][32];       // [gate][b_local][j]
    __shared__ float fcred[2][32];         // [b_local][j]

    const int c   = blockIdx.x;
    const int bg  = c >> 3;
    const int hg  = c & 7;
    const int tid = threadIdx.x;
    const int rg  = tid >> 3;              // hidden unit j (0..31)
    const int kg  = tid & 7;               // 32-k strip

    // Register-resident weights: w2u[g][2i+p] covers k = i*32+kg*4 (+2p)
    unsigned long long w2u[3][16];
#pragma unroll
    for (int g = 0; g < 3; g++)
#pragma unroll
        for (int i = 0; i < 8; i++) {
            const float4 v = *(const float4*)&w_hh[((size_t)(g * HID + hg * 32 + rg)) * HID
                                                   + i * 32 + kg * 4];
            w2u[g][i * 2 + 0] = pk(v.x, v.y);
            w2u[g][i * 2 + 1] = pk(v.z, v.w);
        }

    // Pointwise mapping (tid < 64): (j, b_local)
    const int pj   = tid >> 1;
    const int pb   = tid & 1;
    const int u    = hg * 32 + pj;         // hidden unit index
    const int gbat = bg * 2 + pb;          // global batch
    const float bh_r = b_hh[u];
    const float bh_z = b_hh[HID + u];
    const float bh_n = b_hh[2 * HID + u];
    const float fw   = fc_w[u];

    // Poll/gather mapping: every lane polls one of the 8 column tags
    const unsigned int* tagp = &d_tag[((c & ~7) + (tid & 7)) * 8];
    float h_prev = 0.0f;
    __syncthreads();

    for (int t = 0; t < SEQ; t++) {
        // Prefetch input-side gates (DRAM latency overlaps poll/gather/MAC)
        float xrv = 0.f, xzv = 0.f, xnv = 0.f;
        if (tid < 64) {
            const size_t base = ((size_t)t * G3 + u) * BATCH + gbat;
            xrv = __ldcs(&d_xg[base]);
            xzv = __ldcs(&d_xg[base + (size_t)HID * BATCH]);
            xnv = __ldcs(&d_xg[base + (size_t)2 * HID * BATCH]);
        }

        unsigned long long acc[3][2];
#pragma unroll
        for (int g = 0; g < 3; g++) { acc[g][0] = 0ull; acc[g][1] = 0ull; }

        if (t > 0) {
            // Per-warp poll: all lanes acquire-load (safe ordering lane-wise)
            const unsigned int tt = (unsigned int)t;
            bool ok;
            do {
                unsigned int v;
                asm volatile("ld.acquire.gpu.global.u32 %0, [%1];"
                             : "=r"(v) : "l"(tagp) : "memory");
                ok = __all_sync(0xFFFFFFFFu, v >= tt);
            } while (!ok);
            // Per-warp gather: unit u = tid, 2 batches packed as float2
            {
                const float2 hv = __ldcg((const float2*)&d_hbuf[
                    ((((t - 1) & 1) * BG + bg) * HID + tid) * 2]);
                hsm[0][tid] = hv.x;
                hsm[1][tid] = hv.y;
            }
            __syncthreads();               // hsm fully staged

            // MAC: 96 fma2/thread, LDS.128 broadcast within rg groups
#pragma unroll
            for (int b = 0; b < 2; b++) {
#pragma unroll
                for (int i = 0; i < 8; i++) {
                    const ulonglong2 hh = *(const ulonglong2*)&hsm[b][i * 32 + kg * 4];
#pragma unroll
                    for (int g = 0; g < 3; g++) {
                        fma2(acc[g][b], w2u[g][i * 2 + 0], hh.x);
                        fma2(acc[g][b], w2u[g][i * 2 + 1], hh.y);
                    }
                }
            }
        } else {
            __syncthreads();
        }

        // Reduce over kg (lane bits 0..2) via butterfly shuffles
        float s[3][2];
#pragma unroll
        for (int g = 0; g < 3; g++)
#pragma unroll
            for (int b = 0; b < 2; b++) {
                float2 a = unpk(acc[g][b]);
                s[g][b] = a.x + a.y;
            }
#pragma unroll
        for (int o = 1; o < 8; o <<= 1)
#pragma unroll
            for (int g = 0; g < 3; g++)
#pragma unroll
                for (int b = 0; b < 2; b++)
                    s[g][b] += __shfl_xor_sync(0xFFFFFFFFu, s[g][b], o);
        if ((tid & 7) == 0) {
#pragma unroll
            for (int g = 0; g < 3; g++)
#pragma unroll
                for (int b = 0; b < 2; b++)
                    sout[g][b][rg] = s[g][b];
        }
        __syncthreads();

        if (tid < 64) {
            const float sr = sout[0][pb][pj];
            const float sz = sout[1][pb][pj];
            const float sn = sout[2][pb][pj];
            // torch GRU: n = tanh(xn + r*(hn + bhh_n))
            const float rg_ = 1.0f / (1.0f + __expf(-(xrv + sr + bh_r)));
            const float zg_ = 1.0f / (1.0f + __expf(-(xzv + sz + bh_z)));
            const float ng_ = tanhf(xnv + rg_ * (sn + bh_n));
            const float hnew = (1.0f - zg_) * ng_ + zg_ * h_prev;
            h_prev = hnew;
            // Publish h (64 consecutive floats per CTA -> 2 sectors)
            d_hbuf[(((t & 1) * BG + bg) * HID + u) * 2 + pb] = hnew;
            fcred[pb][pj] = fw * hnew;
        }
        __syncthreads();                   // hbuf STGs + fcred done CTA-wide

        if (tid == 0)                      // publish epoch first (critical path)
            asm volatile("st.release.gpu.global.u32 [%0], %1;"
                         :: "l"(&d_tag[c * 8]), "r"((unsigned)(t + 1)) : "memory");
        if (tid < 2) {                     // fc partial (off critical path)
            float fs = 0.0f;
#pragma unroll
            for (int j = 0; j < 32; j++) fs += fcred[tid][j];
            d_fcp[((size_t)c * SEQ + t) * 2 + tid] = fs;
        }
    }
}

// ---------------------------------------------------------------------------
// Kernel C: out[s][b] = fc_b + sum_hg fcp[(bg*8+hg)][s][b&1]; re-arms tags.
// ---------------------------------------------------------------------------
__global__ void __launch_bounds__(512) final_kernel(const float* __restrict__ fc_b,
                                                    float* __restrict__ out) {
    const int idx = blockIdx.x * 512 + threadIdx.x;
    if (blockIdx.x == 0 && threadIdx.x < NCTA) d_tag[threadIdx.x * 8] = 0u;
    if (idx >= SEQ * BATCH) return;
    const int s  = idx >> 6;
    const int b6 = idx & 63;
    const int bg = b6 >> 1;
    const int bl = b6 & 1;
    float sum = fc_b[0];
#pragma unroll
    for (int hg = 0; hg < HG; hg++)
        sum += d_fcp[((size_t)(bg * HG + hg) * SEQ + s) * 2 + bl];
    out[idx] = sum;
}

extern "C" void kernel_launch(void* const* d_in, const int* in_sizes, int n_in,
                              void* d_out, int out_size) {
    const float* x    = (const float*)d_in[0];
    const float* w_ih = (const float*)d_in[1];
    const float* w_hh = (const float*)d_in[2];
    const float* b_ih = (const float*)d_in[3];
    const float* b_hh = (const float*)d_in[4];
    const float* fc_w = (const float*)d_in[5];
    const float* fc_b = (const float*)d_in[6];
    float* out = (float*)d_out;

    dim3 ga(SEQ, G3 / 64);
    xg_kernel<<<ga, 256>>>(x, w_ih, b_ih);                 // input projections
    scan_kernel<<<NCTA, 256>>>(w_hh, b_hh, fc_w);          // occ-2 dataflow scan
    final_kernel<<<(SEQ * BATCH + 511) / 512, 512>>>(fc_b, out);
}

// round 8
// speedup vs baseline: 1.7602x; 1.7602x over previous
#include <cuda_runtime.h>
#include <cstdint>

#define SEQ   4096
#define BATCH 64
#define INP   64
#define HID   256
#define G3    768
#define BG    16          // batch columns (4 batches each)
#define HG    8           // hidden groups (32 units each)
#define NCTA  (BG*HG)     // 128 scan CTAs, occupancy 1

// Scratch (static device allocations are the sanctioned workaround)
__device__ float d_xg[(size_t)SEQ * G3 * BATCH];     // [s][g][b]
__device__ ulonglong2 d_hmail[2 * BG * 512];         // [par][bg][u*4+b]/2 mail words
__device__ float d_fcp[(size_t)NCTA * SEQ * 4];      // [(bg*8+hg)][t][b4]

__device__ __forceinline__ void fma2(unsigned long long& acc,
                                     unsigned long long a,
                                     unsigned long long b) {
    asm("fma.rn.f32x2 %0, %1, %2, %0;" : "+l"(acc) : "l"(a), "l"(b));
}
__device__ __forceinline__ unsigned long long pk(float a, float b) {
    unsigned long long r;
    asm("mov.b64 %0, {%1, %2};" : "=l"(r) : "f"(a), "f"(b));
    return r;
}
__device__ __forceinline__ float2 unpk(unsigned long long v) {
    float lo, hi;
    asm("mov.b64 {%0, %1}, %2;" : "=f"(lo), "=f"(hi) : "l"(v));
    return make_float2(lo, hi);
}

// ---------------------------------------------------------------------------
// Kernel A: xg[s][g][b] = sum_i x[s][b][i] * w_ih[g][i] + b_ih[g]
// ---------------------------------------------------------------------------
__global__ void __launch_bounds__(256) xg_kernel(const float* __restrict__ x,
                                                 const float* __restrict__ w_ih,
                                                 const float* __restrict__ b_ih) {
    __shared__ float xs[INP][BATCH + 1];
    __shared__ float ws[64][INP];
    const int s   = blockIdx.x;
    const int g0  = blockIdx.y * 64;
    const int tid = threadIdx.x;

    const float* xsrc = x + (size_t)s * BATCH * INP;
    for (int idx = tid; idx < BATCH * INP; idx += 256) {
        int b = idx >> 6, i = idx & 63;
        xs[i][b] = xsrc[idx];
    }
    const float* wsrc = w_ih + (size_t)g0 * INP;
    for (int idx = tid; idx < 64 * INP; idx += 256)
        ws[idx >> 6][idx & 63] = wsrc[idx];
    __syncthreads();

    const int b  = tid & 63;
    const int gg = tid >> 6;
    float xr[INP];
#pragma unroll
    for (int i = 0; i < INP; i++) xr[i] = xs[i][b];

    float acc[16];
#pragma unroll
    for (int u = 0; u < 16; u++) acc[u] = 0.0f;
    const int gb = gg * 16;
#pragma unroll
    for (int i4 = 0; i4 < INP / 4; i4++) {
#pragma unroll
        for (int u = 0; u < 16; u++) {
            float4 w4 = *(const float4*)&ws[gb + u][i4 * 4];
            acc[u] += w4.x * xr[i4 * 4 + 0];
            acc[u] += w4.y * xr[i4 * 4 + 1];
            acc[u] += w4.z * xr[i4 * 4 + 2];
            acc[u] += w4.w * xr[i4 * 4 + 3];
        }
    }
    float* dst = d_xg + ((size_t)s * G3 + g0) * BATCH;
#pragma unroll
    for (int u = 0; u < 16; u++) {
        int gl = gb + u;
        __stcs(&dst[(size_t)gl * BATCH + b], acc[u] + b_ih[g0 + gl]);
    }
}

// ---------------------------------------------------------------------------
// Kernel B: batch-tiled persistent GRU scan with DATA-CARRYING MAILBOX.
// 128 CTAs x 256 threads, occ 1. CTA (bg,hg): 4 batches x 32 hidden units,
// weights register-resident. h exchanged as u64 (epoch<<32 | f32): polling
// the mail IS the gather -> one L2 round trip per step instead of two.
// Reduce+pointwise fully in-warp (butterfly leaves sums in all lanes).
// ---------------------------------------------------------------------------
__global__ void __launch_bounds__(256, 1) scan_kernel(const float* __restrict__ w_hh,
                                                      const float* __restrict__ b_hh,
                                                      const float* __restrict__ fc_w) {
    __shared__ float hsm[4][HID];          // [b_local][k]
    __shared__ float fcred[4][32];         // [b_local][j]

    const int c   = blockIdx.x;
    const int bg  = c & (BG - 1);
    const int hg  = c >> 4;
    const int tid = threadIdx.x;
    const int rg  = tid >> 3;              // hidden unit j (0..31)
    const int kg  = tid & 7;               // 32-k strip

    // Register-resident weights: w2u[g][2i+p] covers k = i*32+kg*4 (+2p)
    unsigned long long w2u[3][16];
#pragma unroll
    for (int g = 0; g < 3; g++)
#pragma unroll
        for (int i = 0; i < 8; i++) {
            const float4 v = *(const float4*)&w_hh[((size_t)(g * HID + hg * 32 + rg)) * HID
                                                   + i * 32 + kg * 4];
            w2u[g][i * 2 + 0] = pk(v.x, v.y);
            w2u[g][i * 2 + 1] = pk(v.z, v.w);
        }

    // Pointwise lanes: kg<4 of each rg group handle batch b=kg of unit rg.
    const bool pw   = (kg < 4);
    const int  u    = hg * 32 + rg;        // own hidden unit
    const int  gbat = bg * 4 + kg;         // own global batch (pw lanes)
    const float bh_r = b_hh[u];
    const float bh_z = b_hh[HID + u];
    const float bh_n = b_hh[2 * HID + u];
    const float fw   = fc_w[u];

    // Mailbox pointers: consumer polls unit tid's 4 batches (2x ulonglong2)
    unsigned long long* const mbase = (unsigned long long*)d_hmail;
    float h_prev = 0.0f;
    __syncthreads();

    for (int t = 0; t < SEQ; t++) {
        // Prefetch input-side gates (overlaps poll + MAC)
        float xrv = 0.f, xzv = 0.f, xnv = 0.f;
        if (pw) {
            const size_t base = ((size_t)t * G3 + u) * BATCH + gbat;
            xrv = __ldcs(&d_xg[base]);
            xzv = __ldcs(&d_xg[base + (size_t)HID * BATCH]);
            xnv = __ldcs(&d_xg[base + (size_t)2 * HID * BATCH]);
        }

        unsigned long long acc[3][4];
#pragma unroll
        for (int g = 0; g < 3; g++)
#pragma unroll
            for (int b = 0; b < 4; b++) acc[g][b] = 0ull;

        if (t > 0) {
            // Poll mail for unit 'tid', epoch t (written by producers at t-1).
            const unsigned long long tt = (unsigned long long)t;
            const ulonglong2* mp = &d_hmail[(((t - 1) & 1) * BG + bg) * 512 + tid * 2];
            unsigned long long m0, m1, m2, m3;
            bool ok;
            do {
                asm volatile("ld.volatile.global.v2.u64 {%0,%1}, [%2];"
                             : "=l"(m0), "=l"(m1) : "l"(mp));
                asm volatile("ld.volatile.global.v2.u64 {%0,%1}, [%2];"
                             : "=l"(m2), "=l"(m3) : "l"(mp + 1));
                ok = ((m0 >> 32) == tt) & ((m1 >> 32) == tt) &
                     ((m2 >> 32) == tt) & ((m3 >> 32) == tt);
            } while (!ok);
            hsm[0][tid] = __uint_as_float((unsigned)m0);
            hsm[1][tid] = __uint_as_float((unsigned)m1);
            hsm[2][tid] = __uint_as_float((unsigned)m2);
            hsm[3][tid] = __uint_as_float((unsigned)m3);
            __syncthreads();               // staging complete CTA-wide

            // MAC: 192 fma2/thread, LDS.128 (8 unique 16B addrs/warp)
#pragma unroll
            for (int b = 0; b < 4; b++) {
#pragma unroll
                for (int i = 0; i < 8; i++) {
                    const ulonglong2 hh = *(const ulonglong2*)&hsm[b][i * 32 + kg * 4];
#pragma unroll
                    for (int g = 0; g < 3; g++) {
                        fma2(acc[g][b], w2u[g][i * 2 + 0], hh.x);
                        fma2(acc[g][b], w2u[g][i * 2 + 1], hh.y);
                    }
                }
            }
        }

        // kg-butterfly: every lane ends with full sums for unit rg
        float s[3][4];
#pragma unroll
        for (int g = 0; g < 3; g++)
#pragma unroll
            for (int b = 0; b < 4; b++) {
                float2 a = unpk(acc[g][b]);
                s[g][b] = a.x + a.y;
            }
#pragma unroll
        for (int o = 1; o < 8; o <<= 1)
#pragma unroll
            for (int g = 0; g < 3; g++)
#pragma unroll
                for (int b = 0; b < 4; b++)
                    s[g][b] += __shfl_xor_sync(0xFFFFFFFFu, s[g][b], o);

        if (pw) {
            // torch GRU: n = tanh(xn + r*(hn + bhh_n)); batch b = kg
            const float rg_ = 1.0f / (1.0f + __expf(-(xrv + s[0][kg] + bh_r)));
            const float zg_ = 1.0f / (1.0f + __expf(-(xzv + s[1][kg] + bh_z)));
            const float ng_ = tanhf(xnv + rg_ * (s[2][kg] + bh_n));
            const float hnew = (1.0f - zg_) * ng_ + zg_ * h_prev;
            h_prev = hnew;
            // Publish mail IMMEDIATELY (critical path): epoch t+1 | value
            const unsigned long long mail =
                ((unsigned long long)(t + 1) << 32) |
                (unsigned long long)__float_as_uint(hnew);
            unsigned long long* maddr =
                mbase + (((t & 1) * BG + bg) * 1024 + u * 4 + kg);
            asm volatile("st.relaxed.gpu.global.u64 [%0], %1;"
                         :: "l"(maddr), "l"(mail) : "memory");
            fcred[kg][rg] = fw * hnew;
        }
        __syncthreads();                   // fcred ready; hsm free for reuse

        if (tid < 4) {                     // fc partial (off critical path)
            float fs = 0.0f;
#pragma unroll
            for (int j = 0; j < 32; j++) fs += fcred[tid][j];
            d_fcp[((size_t)(bg * HG + hg) * SEQ + t) * 4 + tid] = fs;
        }
    }
}

// ---------------------------------------------------------------------------
// Kernel C: out[s][b] = fc_b + sum_hg fcp; re-zeroes the mailbox for replay.
// ---------------------------------------------------------------------------
__global__ void __launch_bounds__(512) final_kernel(const float* __restrict__ fc_b,
                                                    float* __restrict__ out) {
    const int idx = blockIdx.x * 512 + threadIdx.x;
    if (idx < 2 * BG * 1024)                         // 32768 u64 mail words
        ((unsigned long long*)d_hmail)[idx] = 0ull;
    if (idx >= SEQ * BATCH) return;
    const int s  = idx >> 6;
    const int b6 = idx & 63;
    const int bg = b6 >> 2;
    const int bl = b6 & 3;
    float sum = fc_b[0];
#pragma unroll
    for (int hg = 0; hg < HG; hg++)
        sum += d_fcp[((size_t)(bg * HG + hg) * SEQ + s) * 4 + bl];
    out[idx] = sum;
}

extern "C" void kernel_launch(void* const* d_in, const int* in_sizes, int n_in,
                              void* d_out, int out_size) {
    const float* x    = (const float*)d_in[0];
    const float* w_ih = (const float*)d_in[1];
    const float* w_hh = (const float*)d_in[2];
    const float* b_ih = (const float*)d_in[3];
    const float* b_hh = (const float*)d_in[4];
    const float* fc_w = (const float*)d_in[5];
    const float* fc_b = (const float*)d_in[6];
    float* out = (float*)d_out;

    dim3 ga(SEQ, G3 / 64);
    xg_kernel<<<ga, 256>>>(x, w_ih, b_ih);                 // input projections
    scan_kernel<<<NCTA, 256>>>(w_hh, b_hh, fc_w);          // mailbox dataflow scan
    final_kernel<<<(SEQ * BATCH + 511) / 512, 512>>>(fc_b, out);
}

// round 9
// speedup vs baseline: 2.3763x; 1.3500x over previous
#include <cuda_runtime.h>
#include <cstdint>

#define SEQ   4096
#define BATCH 64
#define INP   64
#define HID   256
#define G3    768
#define BG    16          // batch columns (4 batches each)
#define HG    8           // hidden groups (32 units each) = warps/CTA
#define NCTA  (BG*HG)     // 128 scan CTAs, occupancy 1

// Scratch (static device allocations are the sanctioned workaround)
__device__ float d_xg[(size_t)SEQ * G3 * BATCH];     // [s][g][b]
__device__ unsigned long long d_hmail[2 * BG * HG * 32 * 4]; // [par][bg][p][j][b]
__device__ float d_fcp[(size_t)NCTA * SEQ * 4];      // [(bg*8+hg)][t][b4]

__device__ __forceinline__ void fma2(unsigned long long& acc,
                                     unsigned long long a,
                                     unsigned long long b) {
    asm("fma.rn.f32x2 %0, %1, %2, %0;" : "+l"(acc) : "l"(a), "l"(b));
}
__device__ __forceinline__ unsigned long long pk(float a, float b) {
    unsigned long long r;
    asm("mov.b64 %0, {%1, %2};" : "=l"(r) : "f"(a), "f"(b));
    return r;
}
__device__ __forceinline__ float2 unpk(unsigned long long v) {
    float lo, hi;
    asm("mov.b64 {%0, %1}, %2;" : "=f"(lo), "=f"(hi) : "l"(v));
    return make_float2(lo, hi);
}

// ---------------------------------------------------------------------------
// Kernel A: xg[s][g][b] = sum_i x[s][b][i] * w_ih[g][i] + b_ih[g]
// ---------------------------------------------------------------------------
__global__ void __launch_bounds__(256) xg_kernel(const float* __restrict__ x,
                                                 const float* __restrict__ w_ih,
                                                 const float* __restrict__ b_ih) {
    __shared__ float xs[INP][BATCH + 1];
    __shared__ float ws[64][INP];
    const int s   = blockIdx.x;
    const int g0  = blockIdx.y * 64;
    const int tid = threadIdx.x;

    const float* xsrc = x + (size_t)s * BATCH * INP;
    for (int idx = tid; idx < BATCH * INP; idx += 256) {
        int b = idx >> 6, i = idx & 63;
        xs[i][b] = xsrc[idx];
    }
    const float* wsrc = w_ih + (size_t)g0 * INP;
    for (int idx = tid; idx < 64 * INP; idx += 256)
        ws[idx >> 6][idx & 63] = wsrc[idx];
    __syncthreads();

    const int b  = tid & 63;
    const int gg = tid >> 6;
    float xr[INP];
#pragma unroll
    for (int i = 0; i < INP; i++) xr[i] = xs[i][b];

    float acc[16];
#pragma unroll
    for (int u = 0; u < 16; u++) acc[u] = 0.0f;
    const int gb = gg * 16;
#pragma unroll
    for (int i4 = 0; i4 < INP / 4; i4++) {
#pragma unroll
        for (int u = 0; u < 16; u++) {
            float4 w4 = *(const float4*)&ws[gb + u][i4 * 4];
            acc[u] += w4.x * xr[i4 * 4 + 0];
            acc[u] += w4.y * xr[i4 * 4 + 1];
            acc[u] += w4.z * xr[i4 * 4 + 2];
            acc[u] += w4.w * xr[i4 * 4 + 3];
        }
    }
    float* dst = d_xg + ((size_t)s * G3 + g0) * BATCH;
#pragma unroll
    for (int u = 0; u < 16; u++) {
        int gl = gb + u;
        __stcs(&dst[(size_t)gl * BATCH + b], acc[u] + b_ih[g0 + gl]);
    }
}

// ---------------------------------------------------------------------------
// Kernel B: persistent GRU scan, WARP-PER-PRODUCER ready-order consumption.
// CTA (bg,hg): 4 batches x 32 hidden units. Warp w polls ONLY producer w's
// mail block (epoch-carrying u64s), stages to its private hsm[w] (syncwarp
// only), and MACs k-strip [32w,32w+32) immediately -> early producers' MAC
// overlaps waiting for stragglers. Partials combined via smem + 1 bar.
// ---------------------------------------------------------------------------
__global__ void __launch_bounds__(256, 1) scan_kernel(const float* __restrict__ w_hh,
                                                      const float* __restrict__ b_hh,
                                                      const float* __restrict__ fc_w) {
    __shared__ float hsm[HG][4][32];       // [warp][b_local][k_local]
    __shared__ float red[HG][3][128];      // [warp][gate][j*4+b] partials
    __shared__ float fcred[4][32];         // [b_local][j]

    const int c    = blockIdx.x;
    const int bg   = c & (BG - 1);
    const int hg   = c >> 4;
    const int tid  = threadIdx.x;
    const int w    = tid >> 5;             // warp = producer index = k strip
    const int lane = tid & 31;

    // Weights: unit u = hg*32+lane, k in [w*32, w*32+32), k-paired as float2
    unsigned long long w2[3][16];
#pragma unroll
    for (int g = 0; g < 3; g++)
#pragma unroll
        for (int q = 0; q < 8; q++) {
            const float4 v = *(const float4*)&w_hh[
                ((size_t)(g * HID + hg * 32 + lane)) * HID + w * 32 + q * 4];
            w2[g][q * 2 + 0] = pk(v.x, v.y);
            w2[g][q * 2 + 1] = pk(v.z, v.w);
        }

    // Pointwise mapping (tid < 128): unit pj, batch pb
    const int pj = tid >> 2;
    const int pb = tid & 3;
    const int u  = hg * 32 + pj;
    const float bh_r = b_hh[u];
    const float bh_z = b_hh[HID + u];
    const float bh_n = b_hh[2 * HID + u];
    const float fw   = fc_w[u];

    float h_prev = 0.0f;
    __syncthreads();

    for (int t = 0; t < SEQ; t++) {
        // Prefetch input-side gates (overlaps poll + MAC)
        float xrv = 0.f, xzv = 0.f, xnv = 0.f;
        if (tid < 128) {
            const size_t base = ((size_t)t * G3 + u) * BATCH + (bg * 4 + pb);
            xrv = __ldcs(&d_xg[base]);
            xzv = __ldcs(&d_xg[base + (size_t)HID * BATCH]);
            xnv = __ldcs(&d_xg[base + (size_t)2 * HID * BATCH]);
        }

        unsigned long long acc[3][4];      // [gate][b], f32x2 over (k0,k1)
#pragma unroll
        for (int g = 0; g < 3; g++)
#pragma unroll
            for (int b = 0; b < 4; b++) acc[g][b] = 0ull;

        if (t > 0) {
            // Warp w polls ONLY producer w's mail (lane -> unit, 4 batches)
            const unsigned long long tt = (unsigned long long)t;
            const unsigned long long* mp = &d_hmail[
                ((size_t)(((t - 1) & 1) * BG + bg) * HG + w) * 128 + lane * 4];
            unsigned long long m0, m1, m2, m3;
            bool ok;
            do {
                asm volatile("ld.volatile.global.v2.u64 {%0,%1}, [%2];"
                             : "=l"(m0), "=l"(m1) : "l"(mp));
                asm volatile("ld.volatile.global.v2.u64 {%0,%1}, [%2];"
                             : "=l"(m2), "=l"(m3) : "l"(mp + 2));
                ok = __all_sync(0xFFFFFFFFu,
                                ((m0 >> 32) == tt) & ((m1 >> 32) == tt) &
                                ((m2 >> 32) == tt) & ((m3 >> 32) == tt));
            } while (!ok);
            hsm[w][0][lane] = __uint_as_float((unsigned)m0);
            hsm[w][1][lane] = __uint_as_float((unsigned)m1);
            hsm[w][2][lane] = __uint_as_float((unsigned)m2);
            hsm[w][3][lane] = __uint_as_float((unsigned)m3);
            __syncwarp();                  // warp-local staging only

            // Strip MAC: 192 fma2, hsm loads broadcast (same addr all lanes)
#pragma unroll
            for (int b = 0; b < 4; b++) {
#pragma unroll
                for (int q = 0; q < 8; q++) {
                    const ulonglong2 hh = *(const ulonglong2*)&hsm[w][b][q * 4];
#pragma unroll
                    for (int g = 0; g < 3; g++) {
                        fma2(acc[g][b], w2[g][q * 2 + 0], hh.x);
                        fma2(acc[g][b], w2[g][q * 2 + 1], hh.y);
                    }
                }
            }
        }

        // Store per-warp partials: lane = unit, pack 4 batches per gate
#pragma unroll
        for (int g = 0; g < 3; g++) {
            const float2 a0 = unpk(acc[g][0]);
            const float2 a1 = unpk(acc[g][1]);
            const float2 a2 = unpk(acc[g][2]);
            const float2 a3 = unpk(acc[g][3]);
            float4 v = make_float4(a0.x + a0.y, a1.x + a1.y,
                                   a2.x + a2.y, a3.x + a3.y);
            *(float4*)&red[w][g][lane * 4] = v;
        }
        __syncthreads();                   // all warps' partials visible

        if (tid < 128) {
            float sr = 0.f, sz = 0.f, sn = 0.f;
            const int o = pj * 4 + pb;
#pragma unroll
            for (int ww = 0; ww < HG; ww++) {
                sr += red[ww][0][o];
                sz += red[ww][1][o];
                sn += red[ww][2][o];
            }
            // torch GRU: n = tanh(xn + r*(hn + bhh_n))
            const float rg_ = 1.0f / (1.0f + __expf(-(xrv + sr + bh_r)));
            const float zg_ = 1.0f / (1.0f + __expf(-(xzv + sz + bh_z)));
            const float ng_ = tanhf(xnv + rg_ * (sn + bh_n));
            const float hnew = (1.0f - zg_) * ng_ + zg_ * h_prev;
            h_prev = hnew;
            // Publish mail immediately: epoch t+1 | value, parity t&1
            const unsigned long long mail =
                ((unsigned long long)(t + 1) << 32) |
                (unsigned long long)__float_as_uint(hnew);
            unsigned long long* maddr = &d_hmail[
                ((size_t)((t & 1) * BG + bg) * HG + hg) * 128 + pj * 4 + pb];
            asm volatile("st.relaxed.gpu.global.u64 [%0], %1;"
                         :: "l"(maddr), "l"(mail) : "memory");
            fcred[pb][pj] = fw * hnew;
        }
        __syncthreads();                   // fcred ready; red reusable

        if (tid < 4) {                     // fc partial (off critical path)
            float fs = 0.0f;
#pragma unroll
            for (int j = 0; j < 32; j++) fs += fcred[tid][j];
            d_fcp[((size_t)(bg * HG + hg) * SEQ + t) * 4 + tid] = fs;
        }
    }
}

// ---------------------------------------------------------------------------
// Kernel C: out[s][b] = fc_b + sum_hg fcp; re-zeroes the mailbox for replay.
// ---------------------------------------------------------------------------
__global__ void __launch_bounds__(512) final_kernel(const float* __restrict__ fc_b,
                                                    float* __restrict__ out) {
    const int idx = blockIdx.x * 512 + threadIdx.x;
    if (idx < 2 * BG * HG * 32 * 4)                  // 32768 u64 mail words
        d_hmail[idx] = 0ull;
    if (idx >= SEQ * BATCH) return;
    const int s  = idx >> 6;
    const int b6 = idx & 63;
    const int bg = b6 >> 2;
    const int bl = b6 & 3;
    float sum = fc_b[0];
#pragma unroll
    for (int hg = 0; hg < HG; hg++)
        sum += d_fcp[((size_t)(bg * HG + hg) * SEQ + s) * 4 + bl];
    out[idx] = sum;
}

extern "C" void kernel_launch(void* const* d_in, const int* in_sizes, int n_in,
                              void* d_out, int out_size) {
    const float* x    = (const float*)d_in[0];
    const float* w_ih = (const float*)d_in[1];
    const float* w_hh = (const float*)d_in[2];
    const float* b_ih = (const float*)d_in[3];
    const float* b_hh = (const float*)d_in[4];
    const float* fc_w = (const float*)d_in[5];
    const float* fc_b = (const float*)d_in[6];
    float* out = (float*)d_out;

    dim3 ga(SEQ, G3 / 64);
    xg_kernel<<<ga, 256>>>(x, w_ih, b_ih);                 // input projections
    scan_kernel<<<NCTA, 256>>>(w_hh, b_hh, fc_w);          // ready-order scan
    final_kernel<<<(SEQ * BATCH + 511) / 512, 512>>>(fc_b, out);
}